// round 6
// baseline (speedup 1.0000x reference)
#include <cuda_runtime.h>
#include <cuda_bf16.h>
#include <math.h>
#include <stdint.h>

#define NN   50000
#define FH   128

// ===================== scratch (static device globals) =====================
__device__ float g_agg[(size_t)4 * NN * FH];      // 102.4 MB
__device__ float g_deg[4 * NN];
__device__ float g_h1[(size_t)4 * NN * FH];       // 102.4 MB
__device__ float g_hstack[(size_t)4 * NN * FH];   // 102.4 MB
__device__ float g_emb[(size_t)NN * FH];          // 25.6 MB
__device__ __nv_bfloat16 g_whi[18 * 16384], g_wlo[18 * 16384];   // [mat][n][k]

__device__ __forceinline__ void bsplit(float v, __nv_bfloat16& h, __nv_bfloat16& l) {
    h = __float2bfloat16(v);
    l = __float2bfloat16(v - __bfloat162float(h));
}
__device__ __forceinline__ uint32_t pack_bf16(__nv_bfloat16 a, __nv_bfloat16 b) {
    return (uint32_t)__bfloat16_as_ushort(a) | ((uint32_t)__bfloat16_as_ushort(b) << 16);
}
__device__ __forceinline__ void red_add_v4(float* p, float a, float b, float c, float d) {
    asm volatile("red.global.add.v4.f32 [%0], {%1, %2, %3, %4};"
                 :: "l"(p), "f"(a), "f"(b), "f"(c), "f"(d) : "memory");
}
__device__ __forceinline__ void red_add_f32(float* p, float a) {
    asm volatile("red.global.add.f32 [%0], %1;" :: "l"(p), "f"(a) : "memory");
}
__device__ __forceinline__ uint32_t smem_u32(const void* p) {
    uint32_t a;
    asm("{ .reg .u64 t; cvta.to.shared.u64 t, %1; cvt.u32.u64 %0, t; }" : "=r"(a) : "l"(p));
    return a;
}
__device__ __forceinline__ uint32_t swz(uint32_t off) { return off ^ ((off >> 3) & 0x70); }

__device__ __forceinline__ void ldm_x4(uint32_t addr, uint32_t* r) {
    asm volatile("ldmatrix.sync.aligned.m8n8.x4.shared.b16 {%0,%1,%2,%3}, [%4];"
                 : "=r"(r[0]), "=r"(r[1]), "=r"(r[2]), "=r"(r[3]) : "r"(addr));
}
__device__ __forceinline__ void mma16816(float* c, const uint32_t* a, const uint32_t* b) {
    asm volatile("mma.sync.aligned.m16n8k16.row.col.f32.bf16.bf16.f32 "
        "{%0,%1,%2,%3}, {%4,%5,%6,%7}, {%8,%9}, {%0,%1,%2,%3};"
        : "+f"(c[0]), "+f"(c[1]), "+f"(c[2]), "+f"(c[3])
        : "r"(a[0]), "r"(a[1]), "r"(a[2]), "r"(a[3]), "r"(b[0]), "r"(b[1]));
}
__device__ __forceinline__ void cpasync16(uint32_t dst, const void* src) {
    asm volatile("cp.async.ca.shared.global [%0], [%1], 16;"
                 :: "r"(dst), "l"(__cvta_generic_to_global(src)) : "memory");
}
#define CP_COMMIT() asm volatile("cp.async.commit_group;" ::: "memory")
#define CP_WAIT0()  asm volatile("cp.async.wait_group 0;" ::: "memory")

// ===================== small kernels =====================
__global__ void split_weights_kernel(const float* __restrict__ Ws1, const float* __restrict__ Wn1,
                                     const float* __restrict__ Ws2, const float* __restrict__ Wn2,
                                     const float* __restrict__ L1) {
    int g = blockIdx.x * blockDim.x + threadIdx.x;
    if (g >= 18 * 16384) return;
    int m = g >> 14, r = g & 16383, n = r >> 7, k = r & 127;
    const float* s;
    if (m < 4)       s = Ws1 + (size_t)m * 16384;
    else if (m < 8)  s = Wn1 + (size_t)(m - 4) * 16384;
    else if (m < 12) s = Ws2 + (size_t)(m - 8) * 16384;
    else if (m < 16) s = Wn2 + (size_t)(m - 12) * 16384;
    else             s = L1  + (size_t)(m - 16) * 16384;
    float v = s[k * 128 + n];                 // transpose [k][n] -> [n][k]
    __nv_bfloat16 h, l; bsplit(v, h, l);
    g_whi[(size_t)m * 16384 + n * 128 + k] = h;
    g_wlo[(size_t)m * 16384 + n * 128 + k] = l;
}

struct EdgeArgs {
    const int* src[4]; const int* dst[4];
    const float* rows[4];
    int ne[4];
};

// batched scatter: agg[y][dst] += rows[src]; optional degree count; one warp per edge
__global__ void scatter_kernel(EdgeArgs a, int dodeg) {
    int y = blockIdx.y;
    int w = (blockIdx.x * blockDim.x + threadIdx.x) >> 5;
    if (w >= a.ne[y]) return;
    int lane = threadIdx.x & 31;
    int s = __ldg(a.src[y] + w), d = __ldg(a.dst[y] + w);
    float4 v = *(const float4*)(a.rows[y] + (size_t)s * FH + lane * 4);
    float* p = g_agg + ((size_t)y * NN + d) * FH + lane * 4;
    red_add_v4(p, v.x, v.y, v.z, v.w);
    if (dodeg && lane == 0) red_add_f32(&g_deg[y * NN + d], 1.0f);
}

// attention softmax over 4 metapaths -> f32 emb; one warp per node
__global__ void attention_kernel(const float* __restrict__ attW, const float* __restrict__ attB) {
    int n = (blockIdx.x * blockDim.x + threadIdx.x) >> 5;
    if (n >= NN) return;
    int lane = threadIdx.x & 31;
    float4 hv[4]; float logit[4];
#pragma unroll
    for (int k = 0; k < 4; ++k) {
        float4 h4 = *(const float4*)(g_hstack + ((size_t)k * NN + n) * FH + lane * 4);
        float4 w4 = *(const float4*)(attW + k * FH + lane * 4);
        hv[k] = h4;
        float p = h4.x * w4.x + h4.y * w4.y + h4.z * w4.z + h4.w * w4.w;
#pragma unroll
        for (int o = 16; o; o >>= 1) p += __shfl_xor_sync(0xffffffffu, p, o);
        logit[k] = p + attB[k];
    }
    float m = fmaxf(fmaxf(logit[0], logit[1]), fmaxf(logit[2], logit[3]));
    float e[4], s = 0.0f;
#pragma unroll
    for (int k = 0; k < 4; ++k) { e[k] = expf(logit[k] - m); s += e[k]; }
    float is = 1.0f / s;
    float4 o = make_float4(0.f, 0.f, 0.f, 0.f);
#pragma unroll
    for (int k = 0; k < 4; ++k) {
        float w = e[k] * is;
        o.x += w * hv[k].x; o.y += w * hv[k].y; o.z += w * hv[k].z; o.w += w * hv[k].w;
    }
    *(float4*)(g_emb + (size_t)n * FH + lane * 4) = o;
}

// ===================== pipelined mma.sync GEMM =====================
// D[128 x 128] = sum over 2 halves of bf16-split A_half[rows,128](f32 src) @ W_half[n,k]^T
// 3-term split: Ahi*Whi + Ahi*Wlo + Alo*Whi, fp32 accum.
// MODE 0: relu -> f32.  MODE 1: +bias -> f32.  MODE 2: relu + lin2 dot + sigmoid.
#define SB_BIAS 0
#define SB_L2W  512
#define SB_IDX  1024
#define SB_PART 2048
#define SB_TILES 4096
#define TILE_SZ 16384
#define STAGE_SZ (4 * TILE_SZ)
#define SMEM_TOTAL (SB_TILES + 2 * STAGE_SZ)
// tile index within a stage: 0=AHI 1=ALO 2=WHI 3=WLO

// load A chunk (128 rows x 64 f32 cols) into registers; 4 iters x 8 floats per thread
__device__ __forceinline__ void ldg_a(float* v, float* sc, const float* gbase,
                                      const int* sidx, const float* degbase,
                                      int row0, int nrows, int kofs, int tid) {
#pragma unroll
    for (int it = 0; it < 4; ++it) {
        int i = tid + it * 256;
        int r = i >> 3, j = i & 7;
        int grow = row0 + r;
        bool valid = grow < nrows;
        int row = sidx ? sidx[r] : grow;
        const float* p = gbase + (size_t)(valid ? row : 0) * FH + kofs + j * 8;
        float4 a = valid ? *(const float4*)p       : make_float4(0, 0, 0, 0);
        float4 b = valid ? *(const float4*)(p + 4) : make_float4(0, 0, 0, 0);
        v[it * 8 + 0] = a.x; v[it * 8 + 1] = a.y; v[it * 8 + 2] = a.z; v[it * 8 + 3] = a.w;
        v[it * 8 + 4] = b.x; v[it * 8 + 5] = b.y; v[it * 8 + 6] = b.z; v[it * 8 + 7] = b.w;
        sc[it] = degbase ? (1.0f / fmaxf(valid ? __ldg(degbase + grow) : 1.0f, 1.0f)) : 1.0f;
    }
}

// convert + store A regs -> AHI/ALO swizzled tiles
__device__ __forceinline__ void sts_a(const float* v, const float* sc,
                                      uint32_t ahi, uint32_t alo, int tid) {
#pragma unroll
    for (int it = 0; it < 4; ++it) {
        int i = tid + it * 256;
        int r = i >> 3, j = i & 7;
        float s = sc[it];
        uint32_t hp[4], lp[4];
#pragma unroll
        for (int q = 0; q < 4; ++q) {
            float v0 = v[it * 8 + 2 * q] * s, v1 = v[it * 8 + 2 * q + 1] * s;
            __nv_bfloat16 h0, l0, h1, l1;
            bsplit(v0, h0, l0); bsplit(v1, h1, l1);
            hp[q] = pack_bf16(h0, h1); lp[q] = pack_bf16(l0, l1);
        }
        uint32_t off = swz((uint32_t)(r * 128 + j * 16));
        asm volatile("st.shared.v4.b32 [%0], {%1,%2,%3,%4};"
                     :: "r"(ahi + off), "r"(hp[0]), "r"(hp[1]), "r"(hp[2]), "r"(hp[3]));
        asm volatile("st.shared.v4.b32 [%0], {%1,%2,%3,%4};"
                     :: "r"(alo + off), "r"(lp[0]), "r"(lp[1]), "r"(lp[2]), "r"(lp[3]));
    }
}

// async-stage W chunk (bf16 [n][k] source) into swizzled tile
__device__ __forceinline__ void stage_w(uint32_t wdst, const __nv_bfloat16* wsrc,
                                        int kofs, int tid) {
#pragma unroll
    for (int it = 0; it < 4; ++it) {
        int i = tid + it * 256;
        int r = i >> 3, j = i & 7;
        cpasync16(wdst + swz((uint32_t)(r * 128 + j * 16)), wsrc + r * 128 + kofs + j * 8);
    }
}

__device__ __forceinline__ void load_a_frag(uint32_t tb, int wm, int ks, int lane, uint32_t* ra) {
    int q = lane >> 3, r = lane & 7;
    int rofs = ((q & 1) ? 8 : 0) + r;
    int kl = ks * 16 + ((q & 2) ? 8 : 0);
#pragma unroll
    for (int mf = 0; mf < 4; ++mf) {
        uint32_t off = (uint32_t)((wm * 64 + mf * 16 + rofs) * 128 + kl * 2);
        ldm_x4(tb + swz(off), ra + mf * 4);
    }
}
__device__ __forceinline__ void load_w_frag(uint32_t tb, int wn, int ks, int lane, uint32_t* rw) {
    int q = lane >> 3, r = lane & 7;
    int rofs = ((q & 2) ? 8 : 0) + r;
    int kl = ks * 16 + ((q & 1) ? 8 : 0);
#pragma unroll
    for (int pf = 0; pf < 2; ++pf) {
        uint32_t off = (uint32_t)((wn * 32 + pf * 16 + rofs) * 128 + kl * 2);
        ldm_x4(tb + swz(off), rw + pf * 4);
    }
}

template <int MODE>
__global__ void __launch_bounds__(256) mp_gemm_kernel(
    const float* __restrict__ a0base, size_t a0stride,
    const float* __restrict__ a1base, size_t a1stride, int a1deg,
    const int* __restrict__ idx0, const int* __restrict__ idx1,
    int w0mat, int w1mat, int wmatstride,
    const float* __restrict__ bias, int bstride,
    const float* __restrict__ l2w, const float* __restrict__ l2b,
    float* __restrict__ outf, size_t outfstride,
    int nrows)
{
    extern __shared__ char smem[];
    const uint32_t sb = smem_u32(smem);
    const int tid = threadIdx.x, lane = tid & 31, wid = tid >> 5;
    const int wm = wid & 1, wn = wid >> 1;
    const int y = blockIdx.y;
    const int row0 = blockIdx.x * 128;

    float* sbias = (float*)(smem + SB_BIAS);
    float* sl2w  = (float*)(smem + SB_L2W);
    int*   sidx  = (int*)(smem + SB_IDX);       // [2][128]
    float* spart = (float*)(smem + SB_PART);
    if (tid < 128) {
        sbias[tid] = bias[bstride * y + tid];
        if (MODE == 2) {
            sl2w[tid] = l2w[tid];
            int e = row0 + tid;
            sidx[tid]       = (e < nrows) ? __ldg(idx0 + e) : 0;
            sidx[128 + tid] = (e < nrows) ? __ldg(idx1 + e) : 0;
        }
    }
    __syncthreads();

    const float* ab[2] = { a0base + (size_t)y * a0stride, a1base + (size_t)y * a1stride };
    const int* sidxh[2] = { (MODE == 2) ? sidx : nullptr, (MODE == 2) ? sidx + 128 : nullptr };
    const float* degh[2] = { nullptr, a1deg ? (g_deg + y * NN) : nullptr };
    const __nv_bfloat16* whb[2] = { g_whi + (size_t)(w0mat + y * wmatstride) * 16384,
                                    g_whi + (size_t)(w1mat + y * wmatstride) * 16384 };
    const __nv_bfloat16* wlb[2] = { g_wlo + (size_t)(w0mat + y * wmatstride) * 16384,
                                    g_wlo + (size_t)(w1mat + y * wmatstride) * 16384 };

    float acc[4][4][4];
#pragma unroll
    for (int i = 0; i < 4; ++i)
#pragma unroll
        for (int j = 0; j < 4; ++j)
#pragma unroll
            for (int q = 0; q < 4; ++q) acc[i][j][q] = 0.0f;

    float av[32], asc[4];

    // prologue: chunk 0 into stage 0
    ldg_a(av, asc, ab[0], sidxh[0], degh[0], row0, nrows, 0, tid);
    stage_w(sb + SB_TILES + 2 * TILE_SZ, whb[0], 0, tid);
    stage_w(sb + SB_TILES + 3 * TILE_SZ, wlb[0], 0, tid);
    CP_COMMIT();
    sts_a(av, asc, sb + SB_TILES, sb + SB_TILES + TILE_SZ, tid);

#pragma unroll 1
    for (int c = 0; c < 4; ++c) {
        const int b = c & 1;
        CP_WAIT0();
        __syncthreads();
        const int nc = c + 1;
        const uint32_t nsb = sb + SB_TILES + (nc & 1) * STAGE_SZ;
        if (nc < 4) {
            const int nh = nc >> 1, nkc = (nc & 1) * 64;
            ldg_a(av, asc, ab[nh], sidxh[nh], degh[nh], row0, nrows, nkc, tid);
            stage_w(nsb + 2 * TILE_SZ, whb[nh], nkc, tid);
            stage_w(nsb + 3 * TILE_SZ, wlb[nh], nkc, tid);
            CP_COMMIT();
        }
        const uint32_t csb = sb + SB_TILES + b * STAGE_SZ;
        const uint32_t tAHI = csb, tALO = csb + TILE_SZ;
        const uint32_t tWHI = csb + 2 * TILE_SZ, tWLO = csb + 3 * TILE_SZ;
#pragma unroll
        for (int ks = 0; ks < 4; ++ks) {
            uint32_t ra[16], rwh[8], rwl[8];
            load_a_frag(tAHI, wm, ks, lane, ra);
            load_w_frag(tWHI, wn, ks, lane, rwh);
#pragma unroll
            for (int mf = 0; mf < 4; ++mf)
#pragma unroll
                for (int nf = 0; nf < 4; ++nf)
                    mma16816(acc[mf][nf], ra + mf * 4, rwh + nf * 2);
            load_w_frag(tWLO, wn, ks, lane, rwl);
#pragma unroll
            for (int mf = 0; mf < 4; ++mf)
#pragma unroll
                for (int nf = 0; nf < 4; ++nf)
                    mma16816(acc[mf][nf], ra + mf * 4, rwl + nf * 2);
            load_a_frag(tALO, wm, ks, lane, ra);
#pragma unroll
            for (int mf = 0; mf < 4; ++mf)
#pragma unroll
                for (int nf = 0; nf < 4; ++nf)
                    mma16816(acc[mf][nf], ra + mf * 4, rwh + nf * 2);
        }
        if (nc < 4)
            sts_a(av, asc, nsb, nsb + TILE_SZ, tid);
    }

    // ---------------- epilogue ----------------
    // rows = row0 + wm*64 + mf*16 + (lane>>2) [+8]; cols = wn*32 + nf*8 + 2*(lane&3) [+1]
    const int rbase = row0 + wm * 64 + (lane >> 2);
    const int cbase = wn * 32 + 2 * (lane & 3);

    if (MODE == 2) {
        float pr[4][2];
#pragma unroll
        for (int mf = 0; mf < 4; ++mf) { pr[mf][0] = 0.f; pr[mf][1] = 0.f; }
#pragma unroll
        for (int mf = 0; mf < 4; ++mf)
#pragma unroll
            for (int nf = 0; nf < 4; ++nf) {
                int gc = cbase + nf * 8;
                float w0 = sl2w[gc], w1 = sl2w[gc + 1];
                float b0v = sbias[gc], b1v = sbias[gc + 1];
                pr[mf][0] += fmaxf(acc[mf][nf][0] + b0v, 0.f) * w0
                           + fmaxf(acc[mf][nf][1] + b1v, 0.f) * w1;
                pr[mf][1] += fmaxf(acc[mf][nf][2] + b0v, 0.f) * w0
                           + fmaxf(acc[mf][nf][3] + b1v, 0.f) * w1;
            }
#pragma unroll
        for (int mf = 0; mf < 4; ++mf)
#pragma unroll
            for (int hh = 0; hh < 2; ++hh) {
                float p = pr[mf][hh];
                p += __shfl_xor_sync(0xffffffffu, p, 1);
                p += __shfl_xor_sync(0xffffffffu, p, 2);
                if ((lane & 3) == 0)
                    spart[(wm * 64 + mf * 16 + (lane >> 2) + hh * 8) * 4 + wn] = p;
            }
        __syncthreads();
        if (tid < 128) {
            int r = row0 + tid;
            if (r < nrows) {
                float s = spart[tid * 4] + spart[tid * 4 + 1] + spart[tid * 4 + 2] + spart[tid * 4 + 3];
                outf[r] = 1.0f / (1.0f + expf(-(s + l2b[0])));
            }
        }
        return;
    }

#pragma unroll
    for (int mf = 0; mf < 4; ++mf) {
        int r0 = rbase + mf * 16, r1 = r0 + 8;
        bool v0 = r0 < nrows, v1 = r1 < nrows;
#pragma unroll
        for (int nf = 0; nf < 4; ++nf) {
            int gc = cbase + nf * 8;
            float b0v = sbias[gc], b1v = sbias[gc + 1];
            float e0 = acc[mf][nf][0] + b0v, e1 = acc[mf][nf][1] + b1v;
            float e2 = acc[mf][nf][2] + b0v, e3 = acc[mf][nf][3] + b1v;
            if (MODE == 0) {
                e0 = fmaxf(e0, 0.f); e1 = fmaxf(e1, 0.f);
                e2 = fmaxf(e2, 0.f); e3 = fmaxf(e3, 0.f);
            }
            if (v0) *(float2*)(outf + (size_t)y * outfstride + (size_t)r0 * FH + gc) = make_float2(e0, e1);
            if (v1) *(float2*)(outf + (size_t)y * outfstride + (size_t)r1 * FH + gc) = make_float2(e2, e3);
        }
    }
}

// ===================== host =====================
extern "C" void kernel_launch(void* const* d_in, const int* in_sizes, int n_in,
                              void* d_out, int out_size) {
    const float* x    = (const float*)d_in[0];
    const float* Ws1  = (const float*)d_in[1];
    const float* b1   = (const float*)d_in[2];
    const float* Wn1  = (const float*)d_in[3];
    const float* Ws2  = (const float*)d_in[4];
    const float* b2   = (const float*)d_in[5];
    const float* Wn2  = (const float*)d_in[6];
    const float* attW = (const float*)d_in[7];
    const float* attB = (const float*)d_in[8];
    const float* l1W  = (const float*)d_in[9];
    const float* l1b  = (const float*)d_in[10];
    const float* l2W  = (const float*)d_in[11];
    const float* l2b  = (const float*)d_in[12];
    const int* srcs[4] = {(const int*)d_in[13], (const int*)d_in[15],
                          (const int*)d_in[17], (const int*)d_in[19]};
    const int* dsts[4] = {(const int*)d_in[14], (const int*)d_in[16],
                          (const int*)d_in[18], (const int*)d_in[20]};
    const int* ssim = (const int*)d_in[21];
    const int* dsim = (const int*)d_in[22];
    const int  esim = in_sizes[21];

    void *aggP, *degP, *h1P, *hsP, *embP;
    cudaGetSymbolAddress(&aggP, g_agg);
    cudaGetSymbolAddress(&degP, g_deg);
    cudaGetSymbolAddress(&h1P, g_h1);
    cudaGetSymbolAddress(&hsP, g_hstack);
    cudaGetSymbolAddress(&embP, g_emb);

    cudaFuncSetAttribute(mp_gemm_kernel<0>, cudaFuncAttributeMaxDynamicSharedMemorySize, SMEM_TOTAL);
    cudaFuncSetAttribute(mp_gemm_kernel<1>, cudaFuncAttributeMaxDynamicSharedMemorySize, SMEM_TOTAL);
    cudaFuncSetAttribute(mp_gemm_kernel<2>, cudaFuncAttributeMaxDynamicSharedMemorySize, SMEM_TOTAL);

    EdgeArgs ea;
    int max_ne = 0;
    for (int k = 0; k < 4; ++k) {
        ea.src[k] = srcs[k]; ea.dst[k] = dsts[k];
        ea.ne[k] = in_sizes[13 + 2 * k];
        if (ea.ne[k] > max_ne) max_ne = ea.ne[k];
    }

    const int NB = (NN + 127) / 128;
    const size_t NF = (size_t)NN * FH;

    // 0. weight split
    split_weights_kernel<<<(18 * 16384 + 255) / 256, 256>>>(Ws1, Wn1, Ws2, Wn2, l1W);

    // 1. layer-1 aggregation + fused degree count
    cudaMemsetAsync(degP, 0, 4 * NN * sizeof(float));
    cudaMemsetAsync(aggP, 0, 4 * NF * sizeof(float));
    for (int k = 0; k < 4; ++k) ea.rows[k] = x;
    scatter_kernel<<<dim3((max_ne + 7) / 8, 4), 256>>>(ea, 1);

    // 2. layer-1 GEMM: h1 = relu(x@Ws1 + (agg*invdeg)@Wn1 + b1) -> f32
    mp_gemm_kernel<0><<<dim3(NB, 4), 256, SMEM_TOTAL>>>(
        x, 0, (const float*)aggP, NF, 1, nullptr, nullptr,
        0, 4, 1, b1, FH, nullptr, nullptr,
        (float*)h1P, NF, NN);

    // 3. layer-2 aggregation
    cudaMemsetAsync(aggP, 0, 4 * NF * sizeof(float));
    for (int k = 0; k < 4; ++k) ea.rows[k] = (const float*)h1P + (size_t)k * NF;
    scatter_kernel<<<dim3((max_ne + 7) / 8, 4), 256>>>(ea, 0);

    // 4. layer-2 GEMM -> f32 hstack
    mp_gemm_kernel<1><<<dim3(NB, 4), 256, SMEM_TOTAL>>>(
        (const float*)h1P, NF, (const float*)aggP, NF, 1, nullptr, nullptr,
        8, 12, 1, b2, FH, nullptr, nullptr,
        (float*)hsP, NF, NN);

    // 5. attention -> f32 emb
    attention_kernel<<<(NN * 32 + 255) / 256, 256>>>(attW, attB);

    // 6. fused edge scorer: gather-GEMM + relu + lin2 dot + sigmoid
    mp_gemm_kernel<2><<<dim3((esim + 127) / 128, 1), 256, SMEM_TOTAL>>>(
        (const float*)embP, 0, (const float*)embP, 0, 0, ssim, dsim,
        16, 17, 0, l1b, 0, l2W, l2b,
        (float*)d_out, 0, esim);
}